// round 15
// baseline (speedup 1.0000x reference)
#include <cuda_runtime.h>
#include <cuda_fp16.h>
#include <math.h>
#include <stdint.h>

#define P 2048
#define D 1024
#define H 16
#define DH 64
#define HID 32
#define P3D 3072
#define LOG2E 1.44269504088896f

__device__ unsigned int g_q32[P * 512];        // [P][D/2] tau-packed, q*log2e/8
__device__ unsigned int g_k32[P * 512];        // [P][D/2] tau-packed
__device__ unsigned int g_v32[H * 64 * 1024];  // [H][64 d][1024 kvpair tau-slots]
__device__ unsigned int g_xp[P * 512];         // x tau-packed
__device__ unsigned int g_wqp[512 * P3D];      // w_qkv kpair-packed [D/2][3D]
__device__ unsigned int g_wph[512 * D];        // w_proj hi kpair-packed
__device__ unsigned int g_wpl[512 * D];
__device__ unsigned int g_ahi[P * 512];        // att tau-packed
__device__ unsigned int g_bias16[P * 1024];    // bias*log2e, half2-packed [P][P/2]
__device__ int g_qcnt[16];                     // flash->proj dependency counters

__device__ __forceinline__ int tau(int w) { return ((w & 3) << 1) | (w >> 2); }
__device__ __forceinline__ uint32_t h2pk(float a, float b) {
    __half2 h = __floats2half2_rn(a, b);
    return *reinterpret_cast<uint32_t*>(&h);
}
__device__ __forceinline__ uint32_t smem_u32(const void* p) {
    uint32_t a;
    asm("{ .reg .u64 t; cvta.to.shared.u64 t, %1; cvt.u32.u64 %0, t; }" : "=r"(a) : "l"(p));
    return a;
}
__device__ __forceinline__ uint32_t hadd2u(uint32_t a, uint32_t b) {
    uint32_t r; asm("add.f16x2 %0, %1, %2;" : "=r"(r) : "r"(a), "r"(b)); return r;
}
__device__ __forceinline__ uint32_t ex2h2(uint32_t a) {
    uint32_t r; asm("ex2.approx.f16x2 %0, %1;" : "=r"(r) : "r"(a)); return r;
}
__device__ __forceinline__ void mma16(float c[4], uint32_t a0, uint32_t a1,
                                      uint32_t a2, uint32_t a3,
                                      uint32_t b0, uint32_t b1) {
    asm volatile(
        "mma.sync.aligned.m16n8k16.row.col.f32.f16.f16.f32 "
        "{%0,%1,%2,%3},{%4,%5,%6,%7},{%8,%9},{%0,%1,%2,%3};\n"
        : "+f"(c[0]), "+f"(c[1]), "+f"(c[2]), "+f"(c[3])
        : "r"(a0), "r"(a1), "r"(a2), "r"(a3), "r"(b0), "r"(b1));
}
__device__ __forceinline__ void cp16(uint32_t dst, const void* src) {
    asm volatile("cp.async.ca.shared.global [%0], [%1], 16;" :: "r"(dst), "l"(src));
}
#define CP_COMMIT() asm volatile("cp.async.commit_group;" ::: "memory")
#define CP_WAIT0()  asm volatile("cp.async.wait_group 0;" ::: "memory")

// ---------------------------------------------------------------------------
// Single fused pack pre-pass (+ dependency counter reset)
// ---------------------------------------------------------------------------
#define NPA (P * 512)
#define NPB (512 * P3D)
#define NPC (512 * D)

__global__ void pack_all(const float* __restrict__ x, const float* __restrict__ wq,
                         const float* __restrict__ wp,
                         unsigned int* __restrict__ xp, unsigned int* __restrict__ wqp,
                         unsigned int* __restrict__ wph, unsigned int* __restrict__ wpl) {
    int i = blockIdx.x * blockDim.x + threadIdx.x;
    if (i < 16) g_qcnt[i] = 0;
    if (i < NPA) {
        int row = i >> 9, p = i & 511;
        int slot = (p & ~7) | tau(p & 7);
        xp[((size_t)row << 9) + slot] =
            h2pk(x[(size_t)row * 1024 + 2 * p], x[(size_t)row * 1024 + 2 * p + 1]);
    } else if (i < NPA + NPB) {
        int j = i - NPA;
        int kp = j / P3D, n = j % P3D;
        wqp[j] = h2pk(wq[(size_t)(2 * kp) * P3D + n], wq[(size_t)(2 * kp + 1) * P3D + n]);
    } else {
        int j = i - NPA - NPB;
        int kp = j >> 10, n = j & 1023;
        float v0 = wp[(size_t)(2 * kp) * D + n], v1 = wp[(size_t)(2 * kp + 1) * D + n];
        __half h0 = __float2half_rn(v0), h1 = __float2half_rn(v1);
        wph[j] = h2pk(__half2float(h0), __half2float(h1));
        wpl[j] = h2pk(v0 - __half2float(h0), v1 - __half2float(h1));
    }
}

// ---------------------------------------------------------------------------
// Combo kernel: sequential roles (blocks [0,384) qkv, rest rpb). Unchanged.
// ---------------------------------------------------------------------------
#define APu 24
#define BPu 136
#define QKV_SA (128 * APu)
#define QKV_SB (16 * BPu)
#define QKV_ST (QKV_SA + QKV_SB)
#define SM_QKV (2 * QKV_ST * 4)
#define NQKV_BLK 384
#define NRPB_BLK 2048
#define HPt 24

__global__ __launch_bounds__(256, 2) void combo_qkv_rpb(
    const unsigned int* __restrict__ A0, const unsigned int* __restrict__ B0,
    unsigned int* __restrict__ Cq, unsigned int* __restrict__ Ck,
    __half* __restrict__ Cv,
    const float* __restrict__ rel,
    const float* __restrict__ w1, const float* __restrict__ b1,
    const float* __restrict__ w2, const float* __restrict__ b2,
    const float* __restrict__ w3, const float* __restrict__ b3,
    unsigned int* __restrict__ bias16) {
    extern __shared__ unsigned int smu[];
    const int tid = threadIdx.x, lane = tid & 31, warp = tid >> 5;
    const int r4 = lane >> 2, c4l = lane & 3;

    if (blockIdx.x < NQKV_BLK) {
        const uint32_t smb = smem_u32(smu);
        const int wm = warp >> 2, wn = warp & 3;
        const int bx = blockIdx.x;
        const int n0 = (bx % 24) * 128, m0 = (bx / 24) * 128;
        const int Kp = 512;
        const int N = P3D;

        float acc[4][4][4];
        #pragma unroll
        for (int i = 0; i < 4; i++)
            #pragma unroll
            for (int j = 0; j < 4; j++)
                #pragma unroll
                for (int q = 0; q < 4; q++) acc[i][j][q] = 0.f;

        auto load_tile = [&](int kp0, int st) {
            const uint32_t sbase = smb + st * QKV_ST * 4;
            #pragma unroll
            for (int t = tid; t < 512; t += 256) {
                int ar = t >> 2, ac = (t & 3) * 4;
                cp16(sbase + (ar * APu + ac) * 4, &A0[(size_t)(m0 + ar) * Kp + kp0 + ac]);
            }
            #pragma unroll
            for (int t = tid; t < 512; t += 256) {
                int br = t >> 5, bc = (t & 31) * 4;
                cp16(sbase + (QKV_SA + br * BPu + bc) * 4,
                     &B0[(size_t)(kp0 + br) * N + n0 + bc]);
            }
            CP_COMMIT();
        };

        load_tile(0, 0);
        for (int it = 0; it < 32; it++) {
            const int st = it & 1;
            CP_WAIT0();
            __syncthreads();
            if (it + 1 < 32) load_tile((it + 1) * 16, st ^ 1);

            const unsigned int* Ah = smu + st * QKV_ST;
            const unsigned int* Bh = smu + st * QKV_ST + QKV_SA;
            #pragma unroll
            for (int ks = 0; ks < 2; ks++) {
                uint32_t ra[4][4], rb[4][2];
                #pragma unroll
                for (int mt = 0; mt < 4; mt++) {
                    const unsigned int* ap =
                        Ah + (wm * 64 + mt * 16 + r4) * APu + 8 * ks + 2 * c4l;
                    uint2 x0 = *(const uint2*)ap;
                    uint2 x1 = *(const uint2*)(ap + 8 * APu);
                    ra[mt][0] = x0.x; ra[mt][1] = x1.x; ra[mt][2] = x0.y; ra[mt][3] = x1.y;
                }
                #pragma unroll
                for (int nt = 0; nt < 4; nt++) {
                    int cn = wn * 32 + nt * 8 + r4;
                    rb[nt][0] = Bh[(8 * ks + c4l) * BPu + cn];
                    rb[nt][1] = Bh[(8 * ks + c4l + 4) * BPu + cn];
                }
                #pragma unroll
                for (int mt = 0; mt < 4; mt++)
                    #pragma unroll
                    for (int nt = 0; nt < 4; nt++)
                        mma16(acc[mt][nt], ra[mt][0], ra[mt][1], ra[mt][2], ra[mt][3],
                              rb[nt][0], rb[nt][1]);
            }
        }

        #pragma unroll
        for (int mt = 0; mt < 4; mt++)
            #pragma unroll
            for (int nt = 0; nt < 4; nt++) {
                int row = m0 + wm * 64 + mt * 16 + r4;
                int col = n0 + wn * 32 + nt * 8 + 2 * c4l;
                float v0 = acc[mt][nt][0], v1 = acc[mt][nt][1];
                float v2 = acc[mt][nt][2], v3 = acc[mt][nt][3];
                if (col < 2 * D) {
                    const float sc = (col < D) ? (0.125f * LOG2E) : 1.0f;
                    const int dd = col & 1023;
                    const int hh = dd >> 6, dh = dd & 63;
                    const int pr = dh >> 1;
                    const int slot = hh * 32 + ((pr & ~7) | tau(pr & 7));
                    unsigned int* dst = (col < D) ? Cq : Ck;
                    dst[(size_t)row * 512 + slot]       = h2pk(v0 * sc, v1 * sc);
                    dst[(size_t)(row + 8) * 512 + slot] = h2pk(v2 * sc, v3 * sc);
                } else {
                    const int dd = col - 2 * D;
                    const int hh = dd >> 6, dh = dd & 63;
                    const int kp = row >> 1, par = row & 1;
                    const int slot  = (kp & ~7) | tau(kp & 7);
                    const int slot8 = (kp & ~7) | tau((kp & 7) + 4);
                    __half* vb  = Cv + (((size_t)(hh * 64 + dh) << 10) + slot) * 2 + par;
                    __half* vb8 = Cv + (((size_t)(hh * 64 + dh) << 10) + slot8) * 2 + par;
                    vb[0]     = __float2half_rn(v0);
                    vb[2048]  = __float2half_rn(v1);
                    vb8[0]    = __float2half_rn(v2);
                    vb8[2048] = __float2half_rn(v3);
                }
            }
    } else {
        __shared__ unsigned int h1s[8][16][HPt];

        uint32_t w1b0[4];
        float b1c[4][2], b2c[4][2], w3c[4][2];
        uint32_t w2f[2][4][2];
        #pragma unroll
        for (int nt = 0; nt < 4; nt++) {
            const int n = nt * 8 + r4;
            w1b0[nt] = (c4l == 0) ? h2pk(w1[n], w1[HID + n]) : 0u;
            const int cc = nt * 8 + 2 * c4l;
            b1c[nt][0] = b1[cc]; b1c[nt][1] = b1[cc + 1];
            b2c[nt][0] = b2[cc]; b2c[nt][1] = b2[cc + 1];
            w3c[nt][0] = w3[cc]; w3c[nt][1] = w3[cc + 1];
            #pragma unroll
            for (int ks = 0; ks < 2; ks++) {
                w2f[ks][nt][0] = h2pk(w2[(16 * ks + 2 * c4l) * HID + n],
                                      w2[(16 * ks + 2 * c4l + 1) * HID + n]);
                w2f[ks][nt][1] = h2pk(w2[(16 * ks + 2 * c4l + 8) * HID + n],
                                      w2[(16 * ks + 2 * c4l + 9) * HID + n]);
            }
        }
        const float b3v = b3[0];

        unsigned int (*h1)[HPt] = h1s[warp];
        const int gw = (blockIdx.x - NQKV_BLK) * 8 + warp;
        const int nW = NRPB_BLK * 8;
        for (int task = gw; task < (P * P) / 16; task += nW) {
            const int base = task * 16;
            const float2 ra = *(const float2*)&rel[(size_t)(base + r4) * 2];
            const float2 rb = *(const float2*)&rel[(size_t)(base + 8 + r4) * 2];
            const uint32_t a0 = (c4l == 0) ? h2pk(ra.x, ra.y) : 0u;
            const uint32_t a1 = (c4l == 0) ? h2pk(rb.x, rb.y) : 0u;

            float c1[4][4];
            #pragma unroll
            for (int nt = 0; nt < 4; nt++) {
                c1[nt][0] = b1c[nt][0]; c1[nt][1] = b1c[nt][1];
                c1[nt][2] = b1c[nt][0]; c1[nt][3] = b1c[nt][1];
                mma16(c1[nt], a0, a1, 0u, 0u, w1b0[nt], 0u);
            }
            #pragma unroll
            for (int g = 0; g < 2; g++) {
                uint2 w0 = make_uint2(
                    h2pk(fmaxf(c1[2*g][0], 0.f),   fmaxf(c1[2*g][1], 0.f)),
                    h2pk(fmaxf(c1[2*g+1][0], 0.f), fmaxf(c1[2*g+1][1], 0.f)));
                uint2 w1v = make_uint2(
                    h2pk(fmaxf(c1[2*g][2], 0.f),   fmaxf(c1[2*g][3], 0.f)),
                    h2pk(fmaxf(c1[2*g+1][2], 0.f), fmaxf(c1[2*g+1][3], 0.f)));
                *(uint2*)&h1[r4][8 * g + 2 * c4l]     = w0;
                *(uint2*)&h1[r4 + 8][8 * g + 2 * c4l] = w1v;
            }
            __syncwarp();
            float c2[4][4];
            #pragma unroll
            for (int nt = 0; nt < 4; nt++) {
                c2[nt][0] = b2c[nt][0]; c2[nt][1] = b2c[nt][1];
                c2[nt][2] = b2c[nt][0]; c2[nt][3] = b2c[nt][1];
            }
            #pragma unroll
            for (int ks = 0; ks < 2; ks++) {
                uint2 x0 = *(const uint2*)&h1[r4][8 * ks + 2 * c4l];
                uint2 x1 = *(const uint2*)&h1[r4 + 8][8 * ks + 2 * c4l];
                #pragma unroll
                for (int nt = 0; nt < 4; nt++)
                    mma16(c2[nt], x0.x, x1.x, x0.y, x1.y, w2f[ks][nt][0], w2f[ks][nt][1]);
            }
            float o0 = 0.f, o1 = 0.f;
            #pragma unroll
            for (int nt = 0; nt < 4; nt++) {
                o0 += fmaxf(c2[nt][0], 0.f) * w3c[nt][0] + fmaxf(c2[nt][1], 0.f) * w3c[nt][1];
                o1 += fmaxf(c2[nt][2], 0.f) * w3c[nt][0] + fmaxf(c2[nt][3], 0.f) * w3c[nt][1];
            }
            o0 += __shfl_xor_sync(0xffffffffu, o0, 1);
            o0 += __shfl_xor_sync(0xffffffffu, o0, 2);
            o1 += __shfl_xor_sync(0xffffffffu, o1, 1);
            o1 += __shfl_xor_sync(0xffffffffu, o1, 2);
            float o0n = __shfl_down_sync(0xffffffffu, o0, 4);
            float o1n = __shfl_down_sync(0xffffffffu, o1, 4);
            if (c4l == 0 && !(r4 & 1)) {
                const int pb = base >> 1;
                bias16[pb + (r4 >> 1)]     = h2pk((o0 + b3v) * LOG2E, (o0n + b3v) * LOG2E);
                bias16[pb + 4 + (r4 >> 1)] = h2pk((o1 + b3v) * LOG2E, (o1n + b3v) * LOG2E);
            }
            __syncwarp();
        }
    }
}

// ---------------------------------------------------------------------------
// MEGA kernel: blocks [0,256) = flash (16 heads x q-block, grouped by qx);
// blocks [256,512) = proj, gated per-q-block on g_qcnt flags.
// Wave-1 scheduling is bid-ordered -> all flash CTAs resident before most
// proj CTAs; no deadlock (256 flash <= 296 slots).
// ---------------------------------------------------------------------------
#define FQ 128
#define FKV 64
#define NIT (P / FKV)
#define OFF_K0 0
#define OFF_K1 2560
#define OFF_V0 5120
#define OFF_V1 7680
#define OFF_B0 10240
#define OFF_B1 14848
#define BPit 36
#define FLASH_SMEM (19456 * 4)   // 77,824 B
#define ONES2 0x3C003C00u

__global__ __launch_bounds__(256, 2) void mega_flash_proj(
    const unsigned int* __restrict__ q32, const unsigned int* __restrict__ k32,
    const unsigned int* __restrict__ v32, const unsigned int* __restrict__ bias16,
    unsigned int* __restrict__ ahi,
    const unsigned int* __restrict__ wph, const unsigned int* __restrict__ wpl,
    float* __restrict__ out) {
    extern __shared__ unsigned int smu[];
    const uint32_t smb = smem_u32(smu);
    const int tid = threadIdx.x, lane = tid & 31, warp = tid >> 5;
    const int r4 = lane >> 2, c4l = lane & 3;

    if (blockIdx.x < 256) {
        // =========================== FLASH ================================
        const int qx = blockIdx.x >> 4, h = blockIdx.x & 15;
        const int q0 = qx * FQ;
        const int qrow = warp * 16;

        #pragma unroll
        for (int i = 0; i < 2; i++) {
            int idx = tid + i * 256;
            int r = idx >> 3, seg = (idx & 7) * 4;
            cp16(smb + (OFF_K0 + r * 40 + seg) * 4, &k32[(size_t)r * 512 + h * 32 + seg]);
            cp16(smb + (OFF_V0 + r * 40 + seg) * 4, &v32[(size_t)(h * 64 + r) * 1024 + seg]);
        }
        CP_COMMIT();

        #pragma unroll
        for (int i = 0; i < 4; i++) {
            int idx = tid + i * 256;
            int row = idx >> 3, seg = (idx & 7) * 4;
            *(uint4*)&smu[OFF_B0 + row * 40 + seg] =
                *(const uint4*)&q32[(size_t)(q0 + row) * 512 + h * 32 + seg];
        }
        __syncthreads();
        uint32_t qf[4][4];
        #pragma unroll
        for (int ks = 0; ks < 4; ks++) {
            const unsigned int* qp = smu + OFF_B0 + (qrow + r4) * 40 + 8 * ks + 2 * c4l;
            uint2 x0 = *(const uint2*)qp;
            uint2 x1 = *(const uint2*)(qp + 8 * 40);
            qf[ks][0] = x0.x; qf[ks][1] = x1.x; qf[ks][2] = x0.y; qf[ks][3] = x1.y;
        }
        __syncthreads();

        #pragma unroll
        for (int i = 0; i < 4; i++) {
            int idx = tid + i * 256;
            int r = idx >> 3, ch = (idx & 7) * 4;
            cp16(smb + (OFF_B0 + r * BPit + ch) * 4,
                 &bias16[((size_t)(q0 + r) << 10) + ch]);
        }
        CP_COMMIT();

        float oacc[8][4];
        #pragma unroll
        for (int i = 0; i < 8; i++)
            #pragma unroll
            for (int j = 0; j < 4; j++) oacc[i][j] = 0.f;
        float lacc[4] = {0.f, 0.f, 0.f, 0.f};

        for (int it = 0; it < NIT; it++) {
            const int buf = it & 1;
            const unsigned int* Ks = smu + (buf ? OFF_K1 : OFF_K0);
            const unsigned int* Vs = smu + (buf ? OFF_V1 : OFF_V0);
            const unsigned int* Bs = smu + (buf ? OFF_B1 : OFF_B0);
            CP_WAIT0();
            __syncthreads();

            if (it + 1 < NIT) {
                const int kv1 = (it + 1) * FKV;
                const uint32_t ko = buf ? OFF_K0 : OFF_K1;
                const uint32_t vo = buf ? OFF_V0 : OFF_V1;
                const uint32_t bo = buf ? OFF_B0 : OFF_B1;
                #pragma unroll
                for (int i = 0; i < 2; i++) {
                    int idx = tid + i * 256;
                    int r = idx >> 3, seg = (idx & 7) * 4;
                    cp16(smb + (ko + r * 40 + seg) * 4,
                         &k32[(size_t)(kv1 + r) * 512 + h * 32 + seg]);
                    cp16(smb + (vo + r * 40 + seg) * 4,
                         &v32[(size_t)(h * 64 + r) * 1024 + (it + 1) * 32 + seg]);
                }
                #pragma unroll
                for (int i = 0; i < 4; i++) {
                    int idx = tid + i * 256;
                    int r = idx >> 3, ch = (idx & 7) * 4;
                    cp16(smb + (bo + r * BPit + ch) * 4,
                         &bias16[((size_t)(q0 + r) << 10) + (it + 1) * 32 + ch]);
                }
                CP_COMMIT();
            }

            uint32_t pf[4][4];
            #pragma unroll
            for (int g = 0; g < 4; g++) {
                const int ntA = 2 * g, ntB = 2 * g + 1;
                float sA[4] = {0.f, 0.f, 0.f, 0.f}, sB[4] = {0.f, 0.f, 0.f, 0.f};
                #pragma unroll
                for (int ks = 0; ks < 4; ks++) {
                    uint2 ka = *(const uint2*)&Ks[(ntA * 8 + r4) * 40 + 8 * ks + 2 * c4l];
                    uint2 kb = *(const uint2*)&Ks[(ntB * 8 + r4) * 40 + 8 * ks + 2 * c4l];
                    mma16(sA, qf[ks][0], qf[ks][1], qf[ks][2], qf[ks][3], ka.x, ka.y);
                    mma16(sB, qf[ks][0], qf[ks][1], qf[ks][2], qf[ks][3], kb.x, kb.y);
                }
                const uint32_t bA0 = Bs[(qrow + r4) * BPit + ntA * 4 + c4l];
                const uint32_t bA1 = Bs[(qrow + 8 + r4) * BPit + ntA * 4 + c4l];
                const uint32_t bB0 = Bs[(qrow + r4) * BPit + ntB * 4 + c4l];
                const uint32_t bB1 = Bs[(qrow + 8 + r4) * BPit + ntB * 4 + c4l];
                pf[g][0] = ex2h2(hadd2u(h2pk(sA[0], sA[1]), bA0));
                pf[g][1] = ex2h2(hadd2u(h2pk(sA[2], sA[3]), bA1));
                pf[g][2] = ex2h2(hadd2u(h2pk(sB[0], sB[1]), bB0));
                pf[g][3] = ex2h2(hadd2u(h2pk(sB[2], sB[3]), bB1));
            }

            #pragma unroll
            for (int g = 0; g < 4; g++) {
                #pragma unroll
                for (int nt = 0; nt < 8; nt++) {
                    uint2 vb = *(const uint2*)&Vs[(nt * 8 + r4) * 40 + 8 * g + 2 * c4l];
                    mma16(oacc[nt], pf[g][0], pf[g][1], pf[g][2], pf[g][3], vb.x, vb.y);
                }
                mma16(lacc, pf[g][0], pf[g][1], pf[g][2], pf[g][3], ONES2, ONES2);
            }
        }

        const float inv0 = 1.f / lacc[0], inv1 = 1.f / lacc[2];
        #pragma unroll
        for (int nt = 0; nt < 8; nt++) {
            const int slot = h * 32 + 8 * (nt >> 1) + 2 * c4l + (nt & 1);
            ahi[(size_t)(q0 + qrow + r4) * 512 + slot] =
                h2pk(oacc[nt][0] * inv0, oacc[nt][1] * inv0);
            ahi[(size_t)(q0 + qrow + 8 + r4) * 512 + slot] =
                h2pk(oacc[nt][2] * inv1, oacc[nt][3] * inv1);
        }
        // signal completion of this (q-block, head)
        __threadfence();
        __syncthreads();
        if (tid == 0) atomicAdd(&g_qcnt[qx], 1);
    } else {
        // ============================ PROJ ================================
        const int j = blockIdx.x - 256;
        const int n0 = (j & 7) * 128;
        const int m0 = (j >> 3) * 64;
        const int qb = m0 >> 7;
        // wait for all 16 heads of this q-block
        if (tid == 0) {
            while (atomicAdd(&g_qcnt[qb], 0) < 16) __nanosleep(128);
        }
        __syncthreads();
        __threadfence();

        constexpr int SA = 64 * APu;
        constexpr int SB = 16 * BPu;
        constexpr int BLO = SA + SB;
        constexpr int ST  = SA + 2 * SB;
        const int wm = warp >> 2, wn = warp & 3;

        float acc[2][4][4];
        #pragma unroll
        for (int i = 0; i < 2; i++)
            #pragma unroll
            for (int jn = 0; jn < 4; jn++)
                #pragma unroll
                for (int q = 0; q < 4; q++) acc[i][jn][q] = 0.f;

        auto load_tile = [&](int kp0, int st) {
            const uint32_t sbase = smb + st * ST * 4;
            {
                int ar = tid >> 2, ac = (tid & 3) * 4;
                cp16(sbase + (ar * APu + ac) * 4,
                     &ahi[(size_t)(m0 + ar) * 512 + kp0 + ac]);
            }
            #pragma unroll
            for (int t = tid; t < 512; t += 256) {
                int br = t >> 5, bc = (t & 31) * 4;
                cp16(sbase + (SA + br * BPu + bc) * 4, &wph[(size_t)(kp0 + br) * D + n0 + bc]);
                cp16(sbase + (BLO + br * BPu + bc) * 4, &wpl[(size_t)(kp0 + br) * D + n0 + bc]);
            }
            CP_COMMIT();
        };

        load_tile(0, 0);
        for (int it = 0; it < 32; it++) {
            const int st = it & 1;
            CP_WAIT0();
            __syncthreads();
            if (it + 1 < 32) load_tile((it + 1) * 16, st ^ 1);

            const unsigned int* Ah = smu + st * ST;
            const unsigned int* Bh = smu + st * ST + SA;
            const unsigned int* Bl = smu + st * ST + BLO;
            #pragma unroll
            for (int ks = 0; ks < 2; ks++) {
                uint32_t ra[2][4], rb[4][2], lb[4][2];
                #pragma unroll
                for (int mt = 0; mt < 2; mt++) {
                    const unsigned int* ap =
                        Ah + (wm * 32 + mt * 16 + r4) * APu + 8 * ks + 2 * c4l;
                    uint2 x0 = *(const uint2*)ap;
                    uint2 x1 = *(const uint2*)(ap + 8 * APu);
                    ra[mt][0] = x0.x; ra[mt][1] = x1.x; ra[mt][2] = x0.y; ra[mt][3] = x1.y;
                }
                #pragma unroll
                for (int nt = 0; nt < 4; nt++) {
                    int cn = wn * 32 + nt * 8 + r4;
                    rb[nt][0] = Bh[(8 * ks + c4l) * BPu + cn];
                    rb[nt][1] = Bh[(8 * ks + c4l + 4) * BPu + cn];
                    lb[nt][0] = Bl[(8 * ks + c4l) * BPu + cn];
                    lb[nt][1] = Bl[(8 * ks + c4l + 4) * BPu + cn];
                }
                #pragma unroll
                for (int mt = 0; mt < 2; mt++)
                    #pragma unroll
                    for (int nt = 0; nt < 4; nt++) {
                        mma16(acc[mt][nt], ra[mt][0], ra[mt][1], ra[mt][2], ra[mt][3],
                              rb[nt][0], rb[nt][1]);
                        mma16(acc[mt][nt], ra[mt][0], ra[mt][1], ra[mt][2], ra[mt][3],
                              lb[nt][0], lb[nt][1]);
                    }
            }
        }
        #pragma unroll
        for (int mt = 0; mt < 2; mt++)
            #pragma unroll
            for (int nt = 0; nt < 4; nt++) {
                int row = m0 + wm * 32 + mt * 16 + r4;
                int col = n0 + wn * 32 + nt * 8 + 2 * c4l;
                *(float2*)&out[(size_t)row * D + col] =
                    make_float2(acc[mt][nt][0], acc[mt][nt][1]);
                *(float2*)&out[(size_t)(row + 8) * D + col] =
                    make_float2(acc[mt][nt][2], acc[mt][nt][3]);
            }
    }
}

// ---------------------------------------------------------------------------
extern "C" void kernel_launch(void* const* d_in, const int* in_sizes, int n_in,
                              void* d_out, int out_size) {
    const float* x      = (const float*)d_in[0];
    const float* rel    = (const float*)d_in[1];
    const float* w_qkv  = (const float*)d_in[2];
    const float* w_proj = (const float*)d_in[3];
    const float* w1     = (const float*)d_in[4];
    const float* b1     = (const float*)d_in[5];
    const float* w2     = (const float*)d_in[6];
    const float* b2     = (const float*)d_in[7];
    const float* w3     = (const float*)d_in[8];
    const float* b3     = (const float*)d_in[9];
    float* out = (float*)d_out;

    unsigned int *q32, *k32, *v32, *xp, *wqp, *wph, *wpl, *ahi, *bias16;
    cudaGetSymbolAddress((void**)&q32, g_q32);
    cudaGetSymbolAddress((void**)&k32, g_k32);
    cudaGetSymbolAddress((void**)&v32, g_v32);
    cudaGetSymbolAddress((void**)&xp,  g_xp);
    cudaGetSymbolAddress((void**)&wqp, g_wqp);
    cudaGetSymbolAddress((void**)&wph, g_wph);
    cudaGetSymbolAddress((void**)&wpl, g_wpl);
    cudaGetSymbolAddress((void**)&ahi, g_ahi);
    cudaGetSymbolAddress((void**)&bias16, g_bias16);

    cudaFuncSetAttribute(combo_qkv_rpb,
                         cudaFuncAttributeMaxDynamicSharedMemorySize, SM_QKV);
    cudaFuncSetAttribute(mega_flash_proj,
                         cudaFuncAttributeMaxDynamicSharedMemorySize, FLASH_SMEM);

    // 1) fused packs (+ counter reset)
    pack_all<<<(NPA + NPB + NPC) / 256, 256>>>(x, w_qkv, w_proj, xp, wqp, wph, wpl);
    // 2) qkv GEMM || RPB MLP
    combo_qkv_rpb<<<NQKV_BLK + NRPB_BLK, 256, SM_QKV>>>(
        xp, wqp, q32, k32, (__half*)v32, rel, w1, b1, w2, b2, w3, b3, bias16);
    // 3) flash || proj (flag-gated) in ONE launch
    mega_flash_proj<<<512, 256, FLASH_SMEM>>>(
        q32, k32, v32, bias16, ahi, wph, wpl, out);
}

// round 16
// speedup vs baseline: 1.0555x; 1.0555x over previous
#include <cuda_runtime.h>
#include <cuda_fp16.h>
#include <math.h>
#include <stdint.h>

#define P 2048
#define D 1024
#define H 16
#define DH 64
#define HID 32
#define P3D 3072
#define LOG2E 1.44269504088896f

__device__ unsigned int g_q32[P * 512];        // [P][D/2] tau-packed, q*log2e/8
__device__ unsigned int g_k32[P * 512];        // [P][D/2] tau-packed
__device__ unsigned int g_v32[H * 64 * 1024];  // [H][64 d][1024 kvpair tau-slots]
__device__ unsigned int g_xp[P * 512];         // x tau-packed
__device__ unsigned int g_wqp[512 * P3D];      // w_qkv kpair-packed [D/2][3D]
__device__ unsigned int g_wph[512 * D];        // w_proj hi kpair-packed
__device__ unsigned int g_wpl[512 * D];
__device__ unsigned int g_ahi[P * 512];        // att tau-packed
__device__ unsigned int g_bias16[P * 1024];    // bias*log2e, half2-packed [P][P/2]

__device__ __forceinline__ int tau(int w) { return ((w & 3) << 1) | (w >> 2); }
__device__ __forceinline__ uint32_t h2pk(float a, float b) {
    __half2 h = __floats2half2_rn(a, b);
    return *reinterpret_cast<uint32_t*>(&h);
}
__device__ __forceinline__ uint32_t smem_u32(const void* p) {
    uint32_t a;
    asm("{ .reg .u64 t; cvta.to.shared.u64 t, %1; cvt.u32.u64 %0, t; }" : "=r"(a) : "l"(p));
    return a;
}
__device__ __forceinline__ uint32_t hadd2u(uint32_t a, uint32_t b) {
    uint32_t r; asm("add.f16x2 %0, %1, %2;" : "=r"(r) : "r"(a), "r"(b)); return r;
}
__device__ __forceinline__ uint32_t ex2h2(uint32_t a) {
    uint32_t r; asm("ex2.approx.f16x2 %0, %1;" : "=r"(r) : "r"(a)); return r;
}
__device__ __forceinline__ void mma16(float c[4], uint32_t a0, uint32_t a1,
                                      uint32_t a2, uint32_t a3,
                                      uint32_t b0, uint32_t b1) {
    asm volatile(
        "mma.sync.aligned.m16n8k16.row.col.f32.f16.f16.f32 "
        "{%0,%1,%2,%3},{%4,%5,%6,%7},{%8,%9},{%0,%1,%2,%3};\n"
        : "+f"(c[0]), "+f"(c[1]), "+f"(c[2]), "+f"(c[3])
        : "r"(a0), "r"(a1), "r"(a2), "r"(a3), "r"(b0), "r"(b1));
}
__device__ __forceinline__ void cp16(uint32_t dst, const void* src) {
    asm volatile("cp.async.ca.shared.global [%0], [%1], 16;" :: "r"(dst), "l"(src));
}
#define CP_COMMIT() asm volatile("cp.async.commit_group;" ::: "memory")
#define CP_WAIT0()  asm volatile("cp.async.wait_group 0;" ::: "memory")

// ---------------------------------------------------------------------------
// Pack prepass, 4x vectorized (x tau-pack + w_qkv kpair-pack only;
// w_proj pack moved into combo tail).
// ---------------------------------------------------------------------------
#define NPA4 (P * 512 / 4)       // 262144 threads: x
#define NPB4 (512 * P3D / 4)     // 393216 threads: w_qkv
#define NPC4 (512 * D / 4)       // 131072 threads: w_proj (in combo tail)

__global__ void pack_all(const float* __restrict__ x, const float* __restrict__ wq,
                         unsigned int* __restrict__ xp, unsigned int* __restrict__ wqp) {
    int i = blockIdx.x * blockDim.x + threadIdx.x;
    if (i < NPA4) {
        const int row = i >> 7;
        const int p0 = (i & 127) * 4;
        const float4 a = *(const float4*)&x[(size_t)row * 1024 + 2 * p0];
        const float4 b = *(const float4*)&x[(size_t)row * 1024 + 2 * p0 + 4];
        unsigned int* xr = xp + ((size_t)row << 9);
        xr[(p0 & ~7) | tau(p0 & 7)]             = h2pk(a.x, a.y);
        xr[((p0+1) & ~7) | tau((p0+1) & 7)]     = h2pk(a.z, a.w);
        xr[((p0+2) & ~7) | tau((p0+2) & 7)]     = h2pk(b.x, b.y);
        xr[((p0+3) & ~7) | tau((p0+3) & 7)]     = h2pk(b.z, b.w);
    } else {
        const int j = i - NPA4;
        const int kp = j / 768;
        const int n = (j % 768) * 4;
        const float4 u = *(const float4*)&wq[(size_t)(2 * kp) * P3D + n];
        const float4 v = *(const float4*)&wq[(size_t)(2 * kp + 1) * P3D + n];
        *(uint4*)&wqp[(size_t)kp * P3D + n] =
            make_uint4(h2pk(u.x, v.x), h2pk(u.y, v.y), h2pk(u.z, v.z), h2pk(u.w, v.w));
    }
}

// ---------------------------------------------------------------------------
// Combo kernel: blocks [0,384) qkv GEMM; [384,2432) rpb; [2432,2944) w_proj pack.
// ---------------------------------------------------------------------------
#define APu 24
#define BPu 136
#define QKV_SA (128 * APu)
#define QKV_SB (16 * BPu)
#define QKV_ST (QKV_SA + QKV_SB)
#define SM_QKV (2 * QKV_ST * 4)
#define NQKV_BLK 384
#define NRPB_BLK 2048
#define NWP_BLK  (NPC4 / 256)    // 512
#define HPt 24

__global__ __launch_bounds__(256, 2) void combo_qkv_rpb(
    const unsigned int* __restrict__ A0, const unsigned int* __restrict__ B0,
    unsigned int* __restrict__ Cq, unsigned int* __restrict__ Ck,
    __half* __restrict__ Cv,
    const float* __restrict__ rel,
    const float* __restrict__ w1, const float* __restrict__ b1,
    const float* __restrict__ w2, const float* __restrict__ b2,
    const float* __restrict__ w3, const float* __restrict__ b3,
    unsigned int* __restrict__ bias16,
    const float* __restrict__ wp,
    unsigned int* __restrict__ wph, unsigned int* __restrict__ wpl) {
    extern __shared__ unsigned int smu[];
    const int tid = threadIdx.x, lane = tid & 31, warp = tid >> 5;
    const int r4 = lane >> 2, c4l = lane & 3;

    if (blockIdx.x >= NQKV_BLK + NRPB_BLK) {
        // ------------------- w_proj hi/lo pack (tail role) ----------------
        const int j = (blockIdx.x - NQKV_BLK - NRPB_BLK) * 256 + tid;
        const int kp = j >> 8;
        const int n = (j & 255) * 4;
        const float4 u = *(const float4*)&wp[(size_t)(2 * kp) * D + n];
        const float4 v = *(const float4*)&wp[(size_t)(2 * kp + 1) * D + n];
        uint4 whi, wlo;
        {
            float h0 = __half2float(__float2half_rn(u.x)), h1 = __half2float(__float2half_rn(v.x));
            whi.x = h2pk(h0, h1); wlo.x = h2pk(u.x - h0, v.x - h1);
            h0 = __half2float(__float2half_rn(u.y)); h1 = __half2float(__float2half_rn(v.y));
            whi.y = h2pk(h0, h1); wlo.y = h2pk(u.y - h0, v.y - h1);
            h0 = __half2float(__float2half_rn(u.z)); h1 = __half2float(__float2half_rn(v.z));
            whi.z = h2pk(h0, h1); wlo.z = h2pk(u.z - h0, v.z - h1);
            h0 = __half2float(__float2half_rn(u.w)); h1 = __half2float(__float2half_rn(v.w));
            whi.w = h2pk(h0, h1); wlo.w = h2pk(u.w - h0, v.w - h1);
        }
        *(uint4*)&wph[(size_t)kp * D + n] = whi;
        *(uint4*)&wpl[(size_t)kp * D + n] = wlo;
        return;
    }

    if (blockIdx.x < NQKV_BLK) {
        // ------------------------- qkv GEMM body --------------------------
        const uint32_t smb = smem_u32(smu);
        const int wm = warp >> 2, wn = warp & 3;
        const int bx = blockIdx.x;
        const int n0 = (bx % 24) * 128, m0 = (bx / 24) * 128;
        const int Kp = 512;
        const int N = P3D;

        float acc[4][4][4];
        #pragma unroll
        for (int i = 0; i < 4; i++)
            #pragma unroll
            for (int j = 0; j < 4; j++)
                #pragma unroll
                for (int q = 0; q < 4; q++) acc[i][j][q] = 0.f;

        auto load_tile = [&](int kp0, int st) {
            const uint32_t sbase = smb + st * QKV_ST * 4;
            #pragma unroll
            for (int t = tid; t < 512; t += 256) {
                int ar = t >> 2, ac = (t & 3) * 4;
                cp16(sbase + (ar * APu + ac) * 4, &A0[(size_t)(m0 + ar) * Kp + kp0 + ac]);
            }
            #pragma unroll
            for (int t = tid; t < 512; t += 256) {
                int br = t >> 5, bc = (t & 31) * 4;
                cp16(sbase + (QKV_SA + br * BPu + bc) * 4,
                     &B0[(size_t)(kp0 + br) * N + n0 + bc]);
            }
            CP_COMMIT();
        };

        load_tile(0, 0);
        for (int it = 0; it < 32; it++) {
            const int st = it & 1;
            CP_WAIT0();
            __syncthreads();
            if (it + 1 < 32) load_tile((it + 1) * 16, st ^ 1);

            const unsigned int* Ah = smu + st * QKV_ST;
            const unsigned int* Bh = smu + st * QKV_ST + QKV_SA;
            #pragma unroll
            for (int ks = 0; ks < 2; ks++) {
                uint32_t ra[4][4], rb[4][2];
                #pragma unroll
                for (int mt = 0; mt < 4; mt++) {
                    const unsigned int* ap =
                        Ah + (wm * 64 + mt * 16 + r4) * APu + 8 * ks + 2 * c4l;
                    uint2 x0 = *(const uint2*)ap;
                    uint2 x1 = *(const uint2*)(ap + 8 * APu);
                    ra[mt][0] = x0.x; ra[mt][1] = x1.x; ra[mt][2] = x0.y; ra[mt][3] = x1.y;
                }
                #pragma unroll
                for (int nt = 0; nt < 4; nt++) {
                    int cn = wn * 32 + nt * 8 + r4;
                    rb[nt][0] = Bh[(8 * ks + c4l) * BPu + cn];
                    rb[nt][1] = Bh[(8 * ks + c4l + 4) * BPu + cn];
                }
                #pragma unroll
                for (int mt = 0; mt < 4; mt++)
                    #pragma unroll
                    for (int nt = 0; nt < 4; nt++)
                        mma16(acc[mt][nt], ra[mt][0], ra[mt][1], ra[mt][2], ra[mt][3],
                              rb[nt][0], rb[nt][1]);
            }
        }

        #pragma unroll
        for (int mt = 0; mt < 4; mt++)
            #pragma unroll
            for (int nt = 0; nt < 4; nt++) {
                int row = m0 + wm * 64 + mt * 16 + r4;
                int col = n0 + wn * 32 + nt * 8 + 2 * c4l;
                float v0 = acc[mt][nt][0], v1 = acc[mt][nt][1];
                float v2 = acc[mt][nt][2], v3 = acc[mt][nt][3];
                if (col < 2 * D) {
                    const float sc = (col < D) ? (0.125f * LOG2E) : 1.0f;
                    const int dd = col & 1023;
                    const int hh = dd >> 6, dh = dd & 63;
                    const int pr = dh >> 1;
                    const int slot = hh * 32 + ((pr & ~7) | tau(pr & 7));
                    unsigned int* dst = (col < D) ? Cq : Ck;
                    dst[(size_t)row * 512 + slot]       = h2pk(v0 * sc, v1 * sc);
                    dst[(size_t)(row + 8) * 512 + slot] = h2pk(v2 * sc, v3 * sc);
                } else {
                    const int dd = col - 2 * D;
                    const int hh = dd >> 6, dh = dd & 63;
                    const int kp = row >> 1, par = row & 1;
                    const int slot  = (kp & ~7) | tau(kp & 7);
                    const int slot8 = (kp & ~7) | tau((kp & 7) + 4);
                    __half* vb  = Cv + (((size_t)(hh * 64 + dh) << 10) + slot) * 2 + par;
                    __half* vb8 = Cv + (((size_t)(hh * 64 + dh) << 10) + slot8) * 2 + par;
                    vb[0]     = __float2half_rn(v0);
                    vb[2048]  = __float2half_rn(v1);
                    vb8[0]    = __float2half_rn(v2);
                    vb8[2048] = __float2half_rn(v3);
                }
            }
    } else {
        // --------------------------- RPB body ------------------------------
        __shared__ unsigned int h1s[8][16][HPt];

        uint32_t w1b0[4];
        float b1c[4][2], b2c[4][2], w3c[4][2];
        uint32_t w2f[2][4][2];
        #pragma unroll
        for (int nt = 0; nt < 4; nt++) {
            const int n = nt * 8 + r4;
            w1b0[nt] = (c4l == 0) ? h2pk(w1[n], w1[HID + n]) : 0u;
            const int cc = nt * 8 + 2 * c4l;
            b1c[nt][0] = b1[cc]; b1c[nt][1] = b1[cc + 1];
            b2c[nt][0] = b2[cc]; b2c[nt][1] = b2[cc + 1];
            w3c[nt][0] = w3[cc]; w3c[nt][1] = w3[cc + 1];
            #pragma unroll
            for (int ks = 0; ks < 2; ks++) {
                w2f[ks][nt][0] = h2pk(w2[(16 * ks + 2 * c4l) * HID + n],
                                      w2[(16 * ks + 2 * c4l + 1) * HID + n]);
                w2f[ks][nt][1] = h2pk(w2[(16 * ks + 2 * c4l + 8) * HID + n],
                                      w2[(16 * ks + 2 * c4l + 9) * HID + n]);
            }
        }
        const float b3v = b3[0];

        unsigned int (*h1)[HPt] = h1s[warp];
        const int gw = (blockIdx.x - NQKV_BLK) * 8 + warp;
        const int nW = NRPB_BLK * 8;
        for (int task = gw; task < (P * P) / 16; task += nW) {
            const int base = task * 16;
            const float2 ra = *(const float2*)&rel[(size_t)(base + r4) * 2];
            const float2 rb = *(const float2*)&rel[(size_t)(base + 8 + r4) * 2];
            const uint32_t a0 = (c4l == 0) ? h2pk(ra.x, ra.y) : 0u;
            const uint32_t a1 = (c4l == 0) ? h2pk(rb.x, rb.y) : 0u;

            float c1[4][4];
            #pragma unroll
            for (int nt = 0; nt < 4; nt++) {
                c1[nt][0] = b1c[nt][0]; c1[nt][1] = b1c[nt][1];
                c1[nt][2] = b1c[nt][0]; c1[nt][3] = b1c[nt][1];
                mma16(c1[nt], a0, a1, 0u, 0u, w1b0[nt], 0u);
            }
            #pragma unroll
            for (int g = 0; g < 2; g++) {
                uint2 w0 = make_uint2(
                    h2pk(fmaxf(c1[2*g][0], 0.f),   fmaxf(c1[2*g][1], 0.f)),
                    h2pk(fmaxf(c1[2*g+1][0], 0.f), fmaxf(c1[2*g+1][1], 0.f)));
                uint2 w1v = make_uint2(
                    h2pk(fmaxf(c1[2*g][2], 0.f),   fmaxf(c1[2*g][3], 0.f)),
                    h2pk(fmaxf(c1[2*g+1][2], 0.f), fmaxf(c1[2*g+1][3], 0.f)));
                *(uint2*)&h1[r4][8 * g + 2 * c4l]     = w0;
                *(uint2*)&h1[r4 + 8][8 * g + 2 * c4l] = w1v;
            }
            __syncwarp();
            float c2[4][4];
            #pragma unroll
            for (int nt = 0; nt < 4; nt++) {
                c2[nt][0] = b2c[nt][0]; c2[nt][1] = b2c[nt][1];
                c2[nt][2] = b2c[nt][0]; c2[nt][3] = b2c[nt][1];
            }
            #pragma unroll
            for (int ks = 0; ks < 2; ks++) {
                uint2 x0 = *(const uint2*)&h1[r4][8 * ks + 2 * c4l];
                uint2 x1 = *(const uint2*)&h1[r4 + 8][8 * ks + 2 * c4l];
                #pragma unroll
                for (int nt = 0; nt < 4; nt++)
                    mma16(c2[nt], x0.x, x1.x, x0.y, x1.y, w2f[ks][nt][0], w2f[ks][nt][1]);
            }
            float o0 = 0.f, o1 = 0.f;
            #pragma unroll
            for (int nt = 0; nt < 4; nt++) {
                o0 += fmaxf(c2[nt][0], 0.f) * w3c[nt][0] + fmaxf(c2[nt][1], 0.f) * w3c[nt][1];
                o1 += fmaxf(c2[nt][2], 0.f) * w3c[nt][0] + fmaxf(c2[nt][3], 0.f) * w3c[nt][1];
            }
            o0 += __shfl_xor_sync(0xffffffffu, o0, 1);
            o0 += __shfl_xor_sync(0xffffffffu, o0, 2);
            o1 += __shfl_xor_sync(0xffffffffu, o1, 1);
            o1 += __shfl_xor_sync(0xffffffffu, o1, 2);
            float o0n = __shfl_down_sync(0xffffffffu, o0, 4);
            float o1n = __shfl_down_sync(0xffffffffu, o1, 4);
            if (c4l == 0 && !(r4 & 1)) {
                const int pb = base >> 1;
                bias16[pb + (r4 >> 1)]     = h2pk((o0 + b3v) * LOG2E, (o0n + b3v) * LOG2E);
                bias16[pb + 4 + (r4 >> 1)] = h2pk((o1 + b3v) * LOG2E, (o1n + b3v) * LOG2E);
            }
            __syncwarp();
        }
    }
}

// ---------------------------------------------------------------------------
// fp16 proj GEMM (B hi/lo split, 2 MMAs), 128 threads, occupancy 3.
// ---------------------------------------------------------------------------
__global__ __launch_bounds__(128, 3) void gemm_proj(
    const unsigned int* __restrict__ A0,
    const unsigned int* __restrict__ B0, const unsigned int* __restrict__ B1,
    float* __restrict__ C, int M, int N, int K) {
    constexpr int SA = 64 * APu;
    constexpr int SB = 16 * BPu;
    constexpr int BLO = SA + SB;
    constexpr int ST  = SA + 2 * SB;
    extern __shared__ unsigned int smu[];
    const uint32_t smb = smem_u32(smu);

    const int tid = threadIdx.x, lane = tid & 31, warp = tid >> 5;
    const int wn = warp & 3;
    const int m0 = blockIdx.y * 64, n0 = blockIdx.x * 128;
    const int r4 = lane >> 2, c4l = lane & 3;
    const int Kp = K / 2;

    float acc[4][4][4];
    #pragma unroll
    for (int i = 0; i < 4; i++)
        #pragma unroll
        for (int j = 0; j < 4; j++)
            #pragma unroll
            for (int q = 0; q < 4; q++) acc[i][j][q] = 0.f;

    auto load_tile = [&](int kp0, int st) {
        const uint32_t sbase = smb + st * ST * 4;
        #pragma unroll
        for (int t = tid; t < 256; t += 128) {
            int ar = t >> 2, ac = (t & 3) * 4;
            cp16(sbase + (ar * APu + ac) * 4, &A0[(size_t)(m0 + ar) * Kp + kp0 + ac]);
        }
        #pragma unroll
        for (int t = tid; t < 512; t += 128) {
            int br = t >> 5, bc = (t & 31) * 4;
            cp16(sbase + (SA + br * BPu + bc) * 4, &B0[(size_t)(kp0 + br) * N + n0 + bc]);
            cp16(sbase + (BLO + br * BPu + bc) * 4, &B1[(size_t)(kp0 + br) * N + n0 + bc]);
        }
        CP_COMMIT();
    };

    load_tile(0, 0);
    const int niter = K / 32;
    for (int it = 0; it < niter; it++) {
        const int st = it & 1;
        CP_WAIT0();
        __syncthreads();
        if (it + 1 < niter) load_tile((it + 1) * 16, st ^ 1);

        const unsigned int* Ah = smu + st * ST;
        const unsigned int* Bh = smu + st * ST + SA;
        const unsigned int* Bl = smu + st * ST + BLO;
        #pragma unroll
        for (int ks = 0; ks < 2; ks++) {
            uint32_t ra[4][4], rb[4][2], lb[4][2];
            #pragma unroll
            for (int mt = 0; mt < 4; mt++) {
                const unsigned int* ap = Ah + (mt * 16 + r4) * APu + 8 * ks + 2 * c4l;
                uint2 x0 = *(const uint2*)ap;
                uint2 x1 = *(const uint2*)(ap + 8 * APu);
                ra[mt][0] = x0.x; ra[mt][1] = x1.x; ra[mt][2] = x0.y; ra[mt][3] = x1.y;
            }
            #pragma unroll
            for (int nt = 0; nt < 4; nt++) {
                int cn = wn * 32 + nt * 8 + r4;
                rb[nt][0] = Bh[(8 * ks + c4l) * BPu + cn];
                rb[nt][1] = Bh[(8 * ks + c4l + 4) * BPu + cn];
                lb[nt][0] = Bl[(8 * ks + c4l) * BPu + cn];
                lb[nt][1] = Bl[(8 * ks + c4l + 4) * BPu + cn];
            }
            #pragma unroll
            for (int mt = 0; mt < 4; mt++)
                #pragma unroll
                for (int nt = 0; nt < 4; nt++) {
                    mma16(acc[mt][nt], ra[mt][0], ra[mt][1], ra[mt][2], ra[mt][3],
                          rb[nt][0], rb[nt][1]);
                    mma16(acc[mt][nt], ra[mt][0], ra[mt][1], ra[mt][2], ra[mt][3],
                          lb[nt][0], lb[nt][1]);
                }
        }
    }
    #pragma unroll
    for (int mt = 0; mt < 4; mt++)
        #pragma unroll
        for (int nt = 0; nt < 4; nt++) {
            int row = m0 + mt * 16 + r4;
            int col = n0 + wn * 32 + nt * 8 + 2 * c4l;
            *(float2*)&C[(size_t)row * N + col] =
                make_float2(acc[mt][nt][0], acc[mt][nt][1]);
            *(float2*)&C[(size_t)(row + 8) * N + col] =
                make_float2(acc[mt][nt][2], acc[mt][nt][3]);
        }
}

// ---------------------------------------------------------------------------
// Flash attention fp16 (round-14 version): K/V/bias cp.async double-buffered,
// P in registers, fp16x2 softmax, lp via ones-MMA, fixed origin.
// ---------------------------------------------------------------------------
#define FQ 128
#define FKV 64
#define NIT (P / FKV)
#define OFF_K0 0
#define OFF_K1 2560
#define OFF_V0 5120
#define OFF_V1 7680
#define OFF_B0 10240
#define OFF_B1 14848
#define BPit 36
#define FLASH_SMEM (19456 * 4)   // 77,824 B
#define ONES2 0x3C003C00u

__global__ __launch_bounds__(256, 2) void flash10(
    const unsigned int* __restrict__ q32, const unsigned int* __restrict__ k32,
    const unsigned int* __restrict__ v32, const unsigned int* __restrict__ bias16,
    unsigned int* __restrict__ ahi) {
    extern __shared__ unsigned int smu[];
    const uint32_t smb = smem_u32(smu);
    const int tid = threadIdx.x, lane = tid & 31, warp = tid >> 5;
    const int r4 = lane >> 2, c4l = lane & 3;
    const int q0 = blockIdx.x * FQ, h = blockIdx.y;
    const int qrow = warp * 16;

    #pragma unroll
    for (int i = 0; i < 2; i++) {
        int idx = tid + i * 256;
        int r = idx >> 3, seg = (idx & 7) * 4;
        cp16(smb + (OFF_K0 + r * 40 + seg) * 4, &k32[(size_t)r * 512 + h * 32 + seg]);
        cp16(smb + (OFF_V0 + r * 40 + seg) * 4, &v32[(size_t)(h * 64 + r) * 1024 + seg]);
    }
    CP_COMMIT();

    #pragma unroll
    for (int i = 0; i < 4; i++) {
        int idx = tid + i * 256;
        int row = idx >> 3, seg = (idx & 7) * 4;
        *(uint4*)&smu[OFF_B0 + row * 40 + seg] =
            *(const uint4*)&q32[(size_t)(q0 + row) * 512 + h * 32 + seg];
    }
    __syncthreads();
    uint32_t qf[4][4];
    #pragma unroll
    for (int ks = 0; ks < 4; ks++) {
        const unsigned int* qp = smu + OFF_B0 + (qrow + r4) * 40 + 8 * ks + 2 * c4l;
        uint2 x0 = *(const uint2*)qp;
        uint2 x1 = *(const uint2*)(qp + 8 * 40);
        qf[ks][0] = x0.x; qf[ks][1] = x1.x; qf[ks][2] = x0.y; qf[ks][3] = x1.y;
    }
    __syncthreads();

    #pragma unroll
    for (int i = 0; i < 4; i++) {
        int idx = tid + i * 256;
        int r = idx >> 3, ch = (idx & 7) * 4;
        cp16(smb + (OFF_B0 + r * BPit + ch) * 4,
             &bias16[((size_t)(q0 + r) << 10) + ch]);
    }
    CP_COMMIT();

    float oacc[8][4];
    #pragma unroll
    for (int i = 0; i < 8; i++)
        #pragma unroll
        for (int j = 0; j < 4; j++) oacc[i][j] = 0.f;
    float lacc[4] = {0.f, 0.f, 0.f, 0.f};

    for (int it = 0; it < NIT; it++) {
        const int buf = it & 1;
        const unsigned int* Ks = smu + (buf ? OFF_K1 : OFF_K0);
        const unsigned int* Vs = smu + (buf ? OFF_V1 : OFF_V0);
        const unsigned int* Bs = smu + (buf ? OFF_B1 : OFF_B0);
        CP_WAIT0();
        __syncthreads();

        if (it + 1 < NIT) {
            const int kv1 = (it + 1) * FKV;
            const uint32_t ko = buf ? OFF_K0 : OFF_K1;
            const uint32_t vo = buf ? OFF_V0 : OFF_V1;
            const uint32_t bo = buf ? OFF_B0 : OFF_B1;
            #pragma unroll
            for (int i = 0; i < 2; i++) {
                int idx = tid + i * 256;
                int r = idx >> 3, seg = (idx & 7) * 4;
                cp16(smb + (ko + r * 40 + seg) * 4,
                     &k32[(size_t)(kv1 + r) * 512 + h * 32 + seg]);
                cp16(smb + (vo + r * 40 + seg) * 4,
                     &v32[(size_t)(h * 64 + r) * 1024 + (it + 1) * 32 + seg]);
            }
            #pragma unroll
            for (int i = 0; i < 4; i++) {
                int idx = tid + i * 256;
                int r = idx >> 3, ch = (idx & 7) * 4;
                cp16(smb + (bo + r * BPit + ch) * 4,
                     &bias16[((size_t)(q0 + r) << 10) + (it + 1) * 32 + ch]);
            }
            CP_COMMIT();
        }

        uint32_t pf[4][4];
        #pragma unroll
        for (int g = 0; g < 4; g++) {
            const int ntA = 2 * g, ntB = 2 * g + 1;
            float sA[4] = {0.f, 0.f, 0.f, 0.f}, sB[4] = {0.f, 0.f, 0.f, 0.f};
            #pragma unroll
            for (int ks = 0; ks < 4; ks++) {
                uint2 ka = *(const uint2*)&Ks[(ntA * 8 + r4) * 40 + 8 * ks + 2 * c4l];
                uint2 kb = *(const uint2*)&Ks[(ntB * 8 + r4) * 40 + 8 * ks + 2 * c4l];
                mma16(sA, qf[ks][0], qf[ks][1], qf[ks][2], qf[ks][3], ka.x, ka.y);
                mma16(sB, qf[ks][0], qf[ks][1], qf[ks][2], qf[ks][3], kb.x, kb.y);
            }
            const uint32_t bA0 = Bs[(qrow + r4) * BPit + ntA * 4 + c4l];
            const uint32_t bA1 = Bs[(qrow + 8 + r4) * BPit + ntA * 4 + c4l];
            const uint32_t bB0 = Bs[(qrow + r4) * BPit + ntB * 4 + c4l];
            const uint32_t bB1 = Bs[(qrow + 8 + r4) * BPit + ntB * 4 + c4l];
            pf[g][0] = ex2h2(hadd2u(h2pk(sA[0], sA[1]), bA0));
            pf[g][1] = ex2h2(hadd2u(h2pk(sA[2], sA[3]), bA1));
            pf[g][2] = ex2h2(hadd2u(h2pk(sB[0], sB[1]), bB0));
            pf[g][3] = ex2h2(hadd2u(h2pk(sB[2], sB[3]), bB1));
        }

        #pragma unroll
        for (int g = 0; g < 4; g++) {
            #pragma unroll
            for (int nt = 0; nt < 8; nt++) {
                uint2 vb = *(const uint2*)&Vs[(nt * 8 + r4) * 40 + 8 * g + 2 * c4l];
                mma16(oacc[nt], pf[g][0], pf[g][1], pf[g][2], pf[g][3], vb.x, vb.y);
            }
            mma16(lacc, pf[g][0], pf[g][1], pf[g][2], pf[g][3], ONES2, ONES2);
        }
    }

    const float inv0 = 1.f / lacc[0], inv1 = 1.f / lacc[2];
    #pragma unroll
    for (int nt = 0; nt < 8; nt++) {
        const int slot = h * 32 + 8 * (nt >> 1) + 2 * c4l + (nt & 1);
        ahi[(size_t)(q0 + qrow + r4) * 512 + slot] =
            h2pk(oacc[nt][0] * inv0, oacc[nt][1] * inv0);
        ahi[(size_t)(q0 + qrow + 8 + r4) * 512 + slot] =
            h2pk(oacc[nt][2] * inv1, oacc[nt][3] * inv1);
    }
}

// ---------------------------------------------------------------------------
extern "C" void kernel_launch(void* const* d_in, const int* in_sizes, int n_in,
                              void* d_out, int out_size) {
    const float* x      = (const float*)d_in[0];
    const float* rel    = (const float*)d_in[1];
    const float* w_qkv  = (const float*)d_in[2];
    const float* w_proj = (const float*)d_in[3];
    const float* w1     = (const float*)d_in[4];
    const float* b1     = (const float*)d_in[5];
    const float* w2     = (const float*)d_in[6];
    const float* b2     = (const float*)d_in[7];
    const float* w3     = (const float*)d_in[8];
    const float* b3     = (const float*)d_in[9];
    float* out = (float*)d_out;

    unsigned int *q32, *k32, *v32, *xp, *wqp, *wph, *wpl, *ahi, *bias16;
    cudaGetSymbolAddress((void**)&q32, g_q32);
    cudaGetSymbolAddress((void**)&k32, g_k32);
    cudaGetSymbolAddress((void**)&v32, g_v32);
    cudaGetSymbolAddress((void**)&xp,  g_xp);
    cudaGetSymbolAddress((void**)&wqp, g_wqp);
    cudaGetSymbolAddress((void**)&wph, g_wph);
    cudaGetSymbolAddress((void**)&wpl, g_wpl);
    cudaGetSymbolAddress((void**)&ahi, g_ahi);
    cudaGetSymbolAddress((void**)&bias16, g_bias16);

    constexpr int SM_PROJ = 2 * (64 * APu + 2 * 16 * BPu) * 4;
    cudaFuncSetAttribute(combo_qkv_rpb,
                         cudaFuncAttributeMaxDynamicSharedMemorySize, SM_QKV);
    cudaFuncSetAttribute(gemm_proj,
                         cudaFuncAttributeMaxDynamicSharedMemorySize, SM_PROJ);
    cudaFuncSetAttribute(flash10, cudaFuncAttributeMaxDynamicSharedMemorySize, FLASH_SMEM);

    // 1) vectorized packs (x + w_qkv only)
    pack_all<<<(NPA4 + NPB4) / 256, 256>>>(x, w_qkv, xp, wqp);
    // 2) qkv GEMM || RPB MLP || w_proj pack (tail role)
    combo_qkv_rpb<<<NQKV_BLK + NRPB_BLK + NWP_BLK, 256, SM_QKV>>>(
        xp, wqp, q32, k32, (__half*)v32, rel, w1, b1, w2, b2, w3, b3, bias16,
        w_proj, wph, wpl);
    // 3) flash attention
    flash10<<<dim3(P / FQ, H), 256, FLASH_SMEM>>>(q32, k32, v32, bias16, ahi);
    // 4) proj
    gemm_proj<<<dim3(D / 128, P / 64), 128, SM_PROJ>>>(
        ahi, wph, wpl, out, P, D, D);
}

// round 17
// speedup vs baseline: 1.1198x; 1.0610x over previous
#include <cuda_runtime.h>
#include <cuda_fp16.h>
#include <math.h>
#include <stdint.h>

#define P 2048
#define D 1024
#define H 16
#define DH 64
#define HID 32
#define P3D 3072
#define LOG2E 1.44269504088896f

__device__ unsigned int g_q32[P * 512];        // [P][D/2] tau-packed, q*log2e/8
__device__ unsigned int g_k32[P * 512];        // [P][D/2] tau-packed
__device__ unsigned int g_v32[H * 64 * 1024];  // [H][64 d][1024 kvpair tau-slots]
__device__ unsigned int g_xp[P * 512];         // x tau-packed
__device__ unsigned int g_wqp[512 * P3D];      // w_qkv kpair-packed [D/2][3D]
__device__ unsigned int g_wph[512 * D];        // w_proj fp16 kpair-packed
__device__ unsigned int g_ahi[P * 512];        // att tau-packed
__device__ unsigned int g_bias16[P * 1024];    // bias*log2e, half2-packed [P][P/2]

__device__ __forceinline__ int tau(int w) { return ((w & 3) << 1) | (w >> 2); }
__device__ __forceinline__ uint32_t h2pk(float a, float b) {
    __half2 h = __floats2half2_rn(a, b);
    return *reinterpret_cast<uint32_t*>(&h);
}
__device__ __forceinline__ uint32_t smem_u32(const void* p) {
    uint32_t a;
    asm("{ .reg .u64 t; cvta.to.shared.u64 t, %1; cvt.u32.u64 %0, t; }" : "=r"(a) : "l"(p));
    return a;
}
__device__ __forceinline__ uint32_t hadd2u(uint32_t a, uint32_t b) {
    uint32_t r; asm("add.f16x2 %0, %1, %2;" : "=r"(r) : "r"(a), "r"(b)); return r;
}
__device__ __forceinline__ uint32_t ex2h2(uint32_t a) {
    uint32_t r; asm("ex2.approx.f16x2 %0, %1;" : "=r"(r) : "r"(a)); return r;
}
__device__ __forceinline__ void mma16(float c[4], uint32_t a0, uint32_t a1,
                                      uint32_t a2, uint32_t a3,
                                      uint32_t b0, uint32_t b1) {
    asm volatile(
        "mma.sync.aligned.m16n8k16.row.col.f32.f16.f16.f32 "
        "{%0,%1,%2,%3},{%4,%5,%6,%7},{%8,%9},{%0,%1,%2,%3};\n"
        : "+f"(c[0]), "+f"(c[1]), "+f"(c[2]), "+f"(c[3])
        : "r"(a0), "r"(a1), "r"(a2), "r"(a3), "r"(b0), "r"(b1));
}
__device__ __forceinline__ void cp16(uint32_t dst, const void* src) {
    asm volatile("cp.async.ca.shared.global [%0], [%1], 16;" :: "r"(dst), "l"(src));
}
#define CP_COMMIT() asm volatile("cp.async.commit_group;" ::: "memory")
#define CP_WAIT0()  asm volatile("cp.async.wait_group 0;" ::: "memory")

// ---------------------------------------------------------------------------
// Pack prepass, 4x vectorized (x tau-pack + w_qkv kpair-pack;
// w_proj pack in combo tail).
// ---------------------------------------------------------------------------
#define NPA4 (P * 512 / 4)
#define NPB4 (512 * P3D / 4)
#define NPC4 (512 * D / 4)

__global__ void pack_all(const float* __restrict__ x, const float* __restrict__ wq,
                         unsigned int* __restrict__ xp, unsigned int* __restrict__ wqp) {
    int i = blockIdx.x * blockDim.x + threadIdx.x;
    if (i < NPA4) {
        const int row = i >> 7;
        const int p0 = (i & 127) * 4;
        const float4 a = *(const float4*)&x[(size_t)row * 1024 + 2 * p0];
        const float4 b = *(const float4*)&x[(size_t)row * 1024 + 2 * p0 + 4];
        unsigned int* xr = xp + ((size_t)row << 9);
        xr[(p0 & ~7) | tau(p0 & 7)]             = h2pk(a.x, a.y);
        xr[((p0+1) & ~7) | tau((p0+1) & 7)]     = h2pk(a.z, a.w);
        xr[((p0+2) & ~7) | tau((p0+2) & 7)]     = h2pk(b.x, b.y);
        xr[((p0+3) & ~7) | tau((p0+3) & 7)]     = h2pk(b.z, b.w);
    } else {
        const int j = i - NPA4;
        const int kp = j / 768;
        const int n = (j % 768) * 4;
        const float4 u = *(const float4*)&wq[(size_t)(2 * kp) * P3D + n];
        const float4 v = *(const float4*)&wq[(size_t)(2 * kp + 1) * P3D + n];
        *(uint4*)&wqp[(size_t)kp * P3D + n] =
            make_uint4(h2pk(u.x, v.x), h2pk(u.y, v.y), h2pk(u.z, v.z), h2pk(u.w, v.w));
    }
}

// ---------------------------------------------------------------------------
// Combo kernel: blocks [0,384) qkv GEMM; [384,2432) rpb; [2432,2944) w_proj pack.
// ---------------------------------------------------------------------------
#define APu 24
#define BPu 136
#define QKV_SA (128 * APu)
#define QKV_SB (16 * BPu)
#define QKV_ST (QKV_SA + QKV_SB)
#define SM_QKV (2 * QKV_ST * 4)
#define NQKV_BLK 384
#define NRPB_BLK 2048
#define NWP_BLK  (NPC4 / 256)
#define HPt 24

__global__ __launch_bounds__(256, 2) void combo_qkv_rpb(
    const unsigned int* __restrict__ A0, const unsigned int* __restrict__ B0,
    unsigned int* __restrict__ Cq, unsigned int* __restrict__ Ck,
    __half* __restrict__ Cv,
    const float* __restrict__ rel,
    const float* __restrict__ w1, const float* __restrict__ b1,
    const float* __restrict__ w2, const float* __restrict__ b2,
    const float* __restrict__ w3, const float* __restrict__ b3,
    unsigned int* __restrict__ bias16,
    const float* __restrict__ wp, unsigned int* __restrict__ wph) {
    extern __shared__ unsigned int smu[];
    const int tid = threadIdx.x, lane = tid & 31, warp = tid >> 5;
    const int r4 = lane >> 2, c4l = lane & 3;

    if (blockIdx.x >= NQKV_BLK + NRPB_BLK) {
        // ------------------- w_proj fp16 pack (tail role) -----------------
        const int j = (blockIdx.x - NQKV_BLK - NRPB_BLK) * 256 + tid;
        const int kp = j >> 8;
        const int n = (j & 255) * 4;
        const float4 u = *(const float4*)&wp[(size_t)(2 * kp) * D + n];
        const float4 v = *(const float4*)&wp[(size_t)(2 * kp + 1) * D + n];
        *(uint4*)&wph[(size_t)kp * D + n] =
            make_uint4(h2pk(u.x, v.x), h2pk(u.y, v.y), h2pk(u.z, v.z), h2pk(u.w, v.w));
        return;
    }

    if (blockIdx.x < NQKV_BLK) {
        // ------------------------- qkv GEMM body --------------------------
        const uint32_t smb = smem_u32(smu);
        const int wm = warp >> 2, wn = warp & 3;
        const int bx = blockIdx.x;
        const int n0 = (bx % 24) * 128, m0 = (bx / 24) * 128;
        const int Kp = 512;
        const int N = P3D;

        float acc[4][4][4];
        #pragma unroll
        for (int i = 0; i < 4; i++)
            #pragma unroll
            for (int j = 0; j < 4; j++)
                #pragma unroll
                for (int q = 0; q < 4; q++) acc[i][j][q] = 0.f;

        auto load_tile = [&](int kp0, int st) {
            const uint32_t sbase = smb + st * QKV_ST * 4;
            #pragma unroll
            for (int t = tid; t < 512; t += 256) {
                int ar = t >> 2, ac = (t & 3) * 4;
                cp16(sbase + (ar * APu + ac) * 4, &A0[(size_t)(m0 + ar) * Kp + kp0 + ac]);
            }
            #pragma unroll
            for (int t = tid; t < 512; t += 256) {
                int br = t >> 5, bc = (t & 31) * 4;
                cp16(sbase + (QKV_SA + br * BPu + bc) * 4,
                     &B0[(size_t)(kp0 + br) * N + n0 + bc]);
            }
            CP_COMMIT();
        };

        load_tile(0, 0);
        for (int it = 0; it < 32; it++) {
            const int st = it & 1;
            CP_WAIT0();
            __syncthreads();
            if (it + 1 < 32) load_tile((it + 1) * 16, st ^ 1);

            const unsigned int* Ah = smu + st * QKV_ST;
            const unsigned int* Bh = smu + st * QKV_ST + QKV_SA;
            #pragma unroll
            for (int ks = 0; ks < 2; ks++) {
                uint32_t ra[4][4], rb[4][2];
                #pragma unroll
                for (int mt = 0; mt < 4; mt++) {
                    const unsigned int* ap =
                        Ah + (wm * 64 + mt * 16 + r4) * APu + 8 * ks + 2 * c4l;
                    uint2 x0 = *(const uint2*)ap;
                    uint2 x1 = *(const uint2*)(ap + 8 * APu);
                    ra[mt][0] = x0.x; ra[mt][1] = x1.x; ra[mt][2] = x0.y; ra[mt][3] = x1.y;
                }
                #pragma unroll
                for (int nt = 0; nt < 4; nt++) {
                    int cn = wn * 32 + nt * 8 + r4;
                    rb[nt][0] = Bh[(8 * ks + c4l) * BPu + cn];
                    rb[nt][1] = Bh[(8 * ks + c4l + 4) * BPu + cn];
                }
                #pragma unroll
                for (int mt = 0; mt < 4; mt++)
                    #pragma unroll
                    for (int nt = 0; nt < 4; nt++)
                        mma16(acc[mt][nt], ra[mt][0], ra[mt][1], ra[mt][2], ra[mt][3],
                              rb[nt][0], rb[nt][1]);
            }
        }

        #pragma unroll
        for (int mt = 0; mt < 4; mt++)
            #pragma unroll
            for (int nt = 0; nt < 4; nt++) {
                int row = m0 + wm * 64 + mt * 16 + r4;
                int col = n0 + wn * 32 + nt * 8 + 2 * c4l;
                float v0 = acc[mt][nt][0], v1 = acc[mt][nt][1];
                float v2 = acc[mt][nt][2], v3 = acc[mt][nt][3];
                if (col < 2 * D) {
                    const float sc = (col < D) ? (0.125f * LOG2E) : 1.0f;
                    const int dd = col & 1023;
                    const int hh = dd >> 6, dh = dd & 63;
                    const int pr = dh >> 1;
                    const int slot = hh * 32 + ((pr & ~7) | tau(pr & 7));
                    unsigned int* dst = (col < D) ? Cq : Ck;
                    dst[(size_t)row * 512 + slot]       = h2pk(v0 * sc, v1 * sc);
                    dst[(size_t)(row + 8) * 512 + slot] = h2pk(v2 * sc, v3 * sc);
                } else {
                    const int dd = col - 2 * D;
                    const int hh = dd >> 6, dh = dd & 63;
                    const int kp = row >> 1, par = row & 1;
                    const int slot  = (kp & ~7) | tau(kp & 7);
                    const int slot8 = (kp & ~7) | tau((kp & 7) + 4);
                    __half* vb  = Cv + (((size_t)(hh * 64 + dh) << 10) + slot) * 2 + par;
                    __half* vb8 = Cv + (((size_t)(hh * 64 + dh) << 10) + slot8) * 2 + par;
                    vb[0]     = __float2half_rn(v0);
                    vb[2048]  = __float2half_rn(v1);
                    vb8[0]    = __float2half_rn(v2);
                    vb8[2048] = __float2half_rn(v3);
                }
            }
    } else {
        // --------------------------- RPB body ------------------------------
        __shared__ unsigned int h1s[8][16][HPt];

        uint32_t w1b0[4];
        float b1c[4][2], b2c[4][2], w3c[4][2];
        uint32_t w2f[2][4][2];
        #pragma unroll
        for (int nt = 0; nt < 4; nt++) {
            const int n = nt * 8 + r4;
            w1b0[nt] = (c4l == 0) ? h2pk(w1[n], w1[HID + n]) : 0u;
            const int cc = nt * 8 + 2 * c4l;
            b1c[nt][0] = b1[cc]; b1c[nt][1] = b1[cc + 1];
            b2c[nt][0] = b2[cc]; b2c[nt][1] = b2[cc + 1];
            w3c[nt][0] = w3[cc]; w3c[nt][1] = w3[cc + 1];
            #pragma unroll
            for (int ks = 0; ks < 2; ks++) {
                w2f[ks][nt][0] = h2pk(w2[(16 * ks + 2 * c4l) * HID + n],
                                      w2[(16 * ks + 2 * c4l + 1) * HID + n]);
                w2f[ks][nt][1] = h2pk(w2[(16 * ks + 2 * c4l + 8) * HID + n],
                                      w2[(16 * ks + 2 * c4l + 9) * HID + n]);
            }
        }
        const float b3v = b3[0];

        unsigned int (*h1)[HPt] = h1s[warp];
        const int gw = (blockIdx.x - NQKV_BLK) * 8 + warp;
        const int nW = NRPB_BLK * 8;
        for (int task = gw; task < (P * P) / 16; task += nW) {
            const int base = task * 16;
            const float2 ra = *(const float2*)&rel[(size_t)(base + r4) * 2];
            const float2 rb = *(const float2*)&rel[(size_t)(base + 8 + r4) * 2];
            const uint32_t a0 = (c4l == 0) ? h2pk(ra.x, ra.y) : 0u;
            const uint32_t a1 = (c4l == 0) ? h2pk(rb.x, rb.y) : 0u;

            float c1[4][4];
            #pragma unroll
            for (int nt = 0; nt < 4; nt++) {
                c1[nt][0] = b1c[nt][0]; c1[nt][1] = b1c[nt][1];
                c1[nt][2] = b1c[nt][0]; c1[nt][3] = b1c[nt][1];
                mma16(c1[nt], a0, a1, 0u, 0u, w1b0[nt], 0u);
            }
            #pragma unroll
            for (int g = 0; g < 2; g++) {
                uint2 w0 = make_uint2(
                    h2pk(fmaxf(c1[2*g][0], 0.f),   fmaxf(c1[2*g][1], 0.f)),
                    h2pk(fmaxf(c1[2*g+1][0], 0.f), fmaxf(c1[2*g+1][1], 0.f)));
                uint2 w1v = make_uint2(
                    h2pk(fmaxf(c1[2*g][2], 0.f),   fmaxf(c1[2*g][3], 0.f)),
                    h2pk(fmaxf(c1[2*g+1][2], 0.f), fmaxf(c1[2*g+1][3], 0.f)));
                *(uint2*)&h1[r4][8 * g + 2 * c4l]     = w0;
                *(uint2*)&h1[r4 + 8][8 * g + 2 * c4l] = w1v;
            }
            __syncwarp();
            float c2[4][4];
            #pragma unroll
            for (int nt = 0; nt < 4; nt++) {
                c2[nt][0] = b2c[nt][0]; c2[nt][1] = b2c[nt][1];
                c2[nt][2] = b2c[nt][0]; c2[nt][3] = b2c[nt][1];
            }
            #pragma unroll
            for (int ks = 0; ks < 2; ks++) {
                uint2 x0 = *(const uint2*)&h1[r4][8 * ks + 2 * c4l];
                uint2 x1 = *(const uint2*)&h1[r4 + 8][8 * ks + 2 * c4l];
                #pragma unroll
                for (int nt = 0; nt < 4; nt++)
                    mma16(c2[nt], x0.x, x1.x, x0.y, x1.y, w2f[ks][nt][0], w2f[ks][nt][1]);
            }
            float o0 = 0.f, o1 = 0.f;
            #pragma unroll
            for (int nt = 0; nt < 4; nt++) {
                o0 += fmaxf(c2[nt][0], 0.f) * w3c[nt][0] + fmaxf(c2[nt][1], 0.f) * w3c[nt][1];
                o1 += fmaxf(c2[nt][2], 0.f) * w3c[nt][0] + fmaxf(c2[nt][3], 0.f) * w3c[nt][1];
            }
            o0 += __shfl_xor_sync(0xffffffffu, o0, 1);
            o0 += __shfl_xor_sync(0xffffffffu, o0, 2);
            o1 += __shfl_xor_sync(0xffffffffu, o1, 1);
            o1 += __shfl_xor_sync(0xffffffffu, o1, 2);
            float o0n = __shfl_down_sync(0xffffffffu, o0, 4);
            float o1n = __shfl_down_sync(0xffffffffu, o1, 4);
            if (c4l == 0 && !(r4 & 1)) {
                const int pb = base >> 1;
                bias16[pb + (r4 >> 1)]     = h2pk((o0 + b3v) * LOG2E, (o0n + b3v) * LOG2E);
                bias16[pb + 4 + (r4 >> 1)] = h2pk((o1 + b3v) * LOG2E, (o1n + b3v) * LOG2E);
            }
            __syncwarp();
        }
    }
}

// ---------------------------------------------------------------------------
// fp16 proj GEMM, SINGLE MMA (w_proj plain fp16), 128 threads, occupancy 3.
// ---------------------------------------------------------------------------
__global__ __launch_bounds__(128, 3) void gemm_proj(
    const unsigned int* __restrict__ A0, const unsigned int* __restrict__ B0,
    float* __restrict__ C, int M, int N, int K) {
    constexpr int SA = 64 * APu;
    constexpr int SB = 16 * BPu;
    constexpr int ST  = SA + SB;
    extern __shared__ unsigned int smu[];
    const uint32_t smb = smem_u32(smu);

    const int tid = threadIdx.x, lane = tid & 31, warp = tid >> 5;
    const int wn = warp & 3;
    const int m0 = blockIdx.y * 64, n0 = blockIdx.x * 128;
    const int r4 = lane >> 2, c4l = lane & 3;
    const int Kp = K / 2;

    float acc[4][4][4];
    #pragma unroll
    for (int i = 0; i < 4; i++)
        #pragma unroll
        for (int j = 0; j < 4; j++)
            #pragma unroll
            for (int q = 0; q < 4; q++) acc[i][j][q] = 0.f;

    auto load_tile = [&](int kp0, int st) {
        const uint32_t sbase = smb + st * ST * 4;
        #pragma unroll
        for (int t = tid; t < 256; t += 128) {
            int ar = t >> 2, ac = (t & 3) * 4;
            cp16(sbase + (ar * APu + ac) * 4, &A0[(size_t)(m0 + ar) * Kp + kp0 + ac]);
        }
        #pragma unroll
        for (int t = tid; t < 512; t += 128) {
            int br = t >> 5, bc = (t & 31) * 4;
            cp16(sbase + (SA + br * BPu + bc) * 4, &B0[(size_t)(kp0 + br) * N + n0 + bc]);
        }
        CP_COMMIT();
    };

    load_tile(0, 0);
    const int niter = K / 32;
    for (int it = 0; it < niter; it++) {
        const int st = it & 1;
        CP_WAIT0();
        __syncthreads();
        if (it + 1 < niter) load_tile((it + 1) * 16, st ^ 1);

        const unsigned int* Ah = smu + st * ST;
        const unsigned int* Bh = smu + st * ST + SA;
        #pragma unroll
        for (int ks = 0; ks < 2; ks++) {
            uint32_t ra[4][4], rb[4][2];
            #pragma unroll
            for (int mt = 0; mt < 4; mt++) {
                const unsigned int* ap = Ah + (mt * 16 + r4) * APu + 8 * ks + 2 * c4l;
                uint2 x0 = *(const uint2*)ap;
                uint2 x1 = *(const uint2*)(ap + 8 * APu);
                ra[mt][0] = x0.x; ra[mt][1] = x1.x; ra[mt][2] = x0.y; ra[mt][3] = x1.y;
            }
            #pragma unroll
            for (int nt = 0; nt < 4; nt++) {
                int cn = wn * 32 + nt * 8 + r4;
                rb[nt][0] = Bh[(8 * ks + c4l) * BPu + cn];
                rb[nt][1] = Bh[(8 * ks + c4l + 4) * BPu + cn];
            }
            #pragma unroll
            for (int mt = 0; mt < 4; mt++)
                #pragma unroll
                for (int nt = 0; nt < 4; nt++)
                    mma16(acc[mt][nt], ra[mt][0], ra[mt][1], ra[mt][2], ra[mt][3],
                          rb[nt][0], rb[nt][1]);
        }
    }
    #pragma unroll
    for (int mt = 0; mt < 4; mt++)
        #pragma unroll
        for (int nt = 0; nt < 4; nt++) {
            int row = m0 + mt * 16 + r4;
            int col = n0 + wn * 32 + nt * 8 + 2 * c4l;
            *(float2*)&C[(size_t)row * N + col] =
                make_float2(acc[mt][nt][0], acc[mt][nt][1]);
            *(float2*)&C[(size_t)(row + 8) * N + col] =
                make_float2(acc[mt][nt][2], acc[mt][nt][3]);
        }
}

// ---------------------------------------------------------------------------
// Flash attention fp16 (round-14/16 version, unchanged).
// ---------------------------------------------------------------------------
#define FQ 128
#define FKV 64
#define NIT (P / FKV)
#define OFF_K0 0
#define OFF_K1 2560
#define OFF_V0 5120
#define OFF_V1 7680
#define OFF_B0 10240
#define OFF_B1 14848
#define BPit 36
#define FLASH_SMEM (19456 * 4)
#define ONES2 0x3C003C00u

__global__ __launch_bounds__(256, 2) void flash10(
    const unsigned int* __restrict__ q32, const unsigned int* __restrict__ k32,
    const unsigned int* __restrict__ v32, const unsigned int* __restrict__ bias16,
    unsigned int* __restrict__ ahi) {
    extern __shared__ unsigned int smu[];
    const uint32_t smb = smem_u32(smu);
    const int tid = threadIdx.x, lane = tid & 31, warp = tid >> 5;
    const int r4 = lane >> 2, c4l = lane & 3;
    const int q0 = blockIdx.x * FQ, h = blockIdx.y;
    const int qrow = warp * 16;

    #pragma unroll
    for (int i = 0; i < 2; i++) {
        int idx = tid + i * 256;
        int r = idx >> 3, seg = (idx & 7) * 4;
        cp16(smb + (OFF_K0 + r * 40 + seg) * 4, &k32[(size_t)r * 512 + h * 32 + seg]);
        cp16(smb + (OFF_V0 + r * 40 + seg) * 4, &v32[(size_t)(h * 64 + r) * 1024 + seg]);
    }
    CP_COMMIT();

    #pragma unroll
    for (int i = 0; i < 4; i++) {
        int idx = tid + i * 256;
        int row = idx >> 3, seg = (idx & 7) * 4;
        *(uint4*)&smu[OFF_B0 + row * 40 + seg] =
            *(const uint4*)&q32[(size_t)(q0 + row) * 512 + h * 32 + seg];
    }
    __syncthreads();
    uint32_t qf[4][4];
    #pragma unroll
    for (int ks = 0; ks < 4; ks++) {
        const unsigned int* qp = smu + OFF_B0 + (qrow + r4) * 40 + 8 * ks + 2 * c4l;
        uint2 x0 = *(const uint2*)qp;
        uint2 x1 = *(const uint2*)(qp + 8 * 40);
        qf[ks][0] = x0.x; qf[ks][1] = x1.x; qf[ks][2] = x0.y; qf[ks][3] = x1.y;
    }
    __syncthreads();

    #pragma unroll
    for (int i = 0; i < 4; i++) {
        int idx = tid + i * 256;
        int r = idx >> 3, ch = (idx & 7) * 4;
        cp16(smb + (OFF_B0 + r * BPit + ch) * 4,
             &bias16[((size_t)(q0 + r) << 10) + ch]);
    }
    CP_COMMIT();

    float oacc[8][4];
    #pragma unroll
    for (int i = 0; i < 8; i++)
        #pragma unroll
        for (int j = 0; j < 4; j++) oacc[i][j] = 0.f;
    float lacc[4] = {0.f, 0.f, 0.f, 0.f};

    for (int it = 0; it < NIT; it++) {
        const int buf = it & 1;
        const unsigned int* Ks = smu + (buf ? OFF_K1 : OFF_K0);
        const unsigned int* Vs = smu + (buf ? OFF_V1 : OFF_V0);
        const unsigned int* Bs = smu + (buf ? OFF_B1 : OFF_B0);
        CP_WAIT0();
        __syncthreads();

        if (it + 1 < NIT) {
            const int kv1 = (it + 1) * FKV;
            const uint32_t ko = buf ? OFF_K0 : OFF_K1;
            const uint32_t vo = buf ? OFF_V0 : OFF_V1;
            const uint32_t bo = buf ? OFF_B0 : OFF_B1;
            #pragma unroll
            for (int i = 0; i < 2; i++) {
                int idx = tid + i * 256;
                int r = idx >> 3, seg = (idx & 7) * 4;
                cp16(smb + (ko + r * 40 + seg) * 4,
                     &k32[(size_t)(kv1 + r) * 512 + h * 32 + seg]);
                cp16(smb + (vo + r * 40 + seg) * 4,
                     &v32[(size_t)(h * 64 + r) * 1024 + (it + 1) * 32 + seg]);
            }
            #pragma unroll
            for (int i = 0; i < 4; i++) {
                int idx = tid + i * 256;
                int r = idx >> 3, ch = (idx & 7) * 4;
                cp16(smb + (bo + r * BPit + ch) * 4,
                     &bias16[((size_t)(q0 + r) << 10) + (it + 1) * 32 + ch]);
            }
            CP_COMMIT();
        }

        uint32_t pf[4][4];
        #pragma unroll
        for (int g = 0; g < 4; g++) {
            const int ntA = 2 * g, ntB = 2 * g + 1;
            float sA[4] = {0.f, 0.f, 0.f, 0.f}, sB[4] = {0.f, 0.f, 0.f, 0.f};
            #pragma unroll
            for (int ks = 0; ks < 4; ks++) {
                uint2 ka = *(const uint2*)&Ks[(ntA * 8 + r4) * 40 + 8 * ks + 2 * c4l];
                uint2 kb = *(const uint2*)&Ks[(ntB * 8 + r4) * 40 + 8 * ks + 2 * c4l];
                mma16(sA, qf[ks][0], qf[ks][1], qf[ks][2], qf[ks][3], ka.x, ka.y);
                mma16(sB, qf[ks][0], qf[ks][1], qf[ks][2], qf[ks][3], kb.x, kb.y);
            }
            const uint32_t bA0 = Bs[(qrow + r4) * BPit + ntA * 4 + c4l];
            const uint32_t bA1 = Bs[(qrow + 8 + r4) * BPit + ntA * 4 + c4l];
            const uint32_t bB0 = Bs[(qrow + r4) * BPit + ntB * 4 + c4l];
            const uint32_t bB1 = Bs[(qrow + 8 + r4) * BPit + ntB * 4 + c4l];
            pf[g][0] = ex2h2(hadd2u(h2pk(sA[0], sA[1]), bA0));
            pf[g][1] = ex2h2(hadd2u(h2pk(sA[2], sA[3]), bA1));
            pf[g][2] = ex2h2(hadd2u(h2pk(sB[0], sB[1]), bB0));
            pf[g][3] = ex2h2(hadd2u(h2pk(sB[2], sB[3]), bB1));
        }

        #pragma unroll
        for (int g = 0; g < 4; g++) {
            #pragma unroll
            for (int nt = 0; nt < 8; nt++) {
                uint2 vb = *(const uint2*)&Vs[(nt * 8 + r4) * 40 + 8 * g + 2 * c4l];
                mma16(oacc[nt], pf[g][0], pf[g][1], pf[g][2], pf[g][3], vb.x, vb.y);
            }
            mma16(lacc, pf[g][0], pf[g][1], pf[g][2], pf[g][3], ONES2, ONES2);
        }
    }

    const float inv0 = 1.f / lacc[0], inv1 = 1.f / lacc[2];
    #pragma unroll
    for (int nt = 0; nt < 8; nt++) {
        const int slot = h * 32 + 8 * (nt >> 1) + 2 * c4l + (nt & 1);
        ahi[(size_t)(q0 + qrow + r4) * 512 + slot] =
            h2pk(oacc[nt][0] * inv0, oacc[nt][1] * inv0);
        ahi[(size_t)(q0 + qrow + 8 + r4) * 512 + slot] =
            h2pk(oacc[nt][2] * inv1, oacc[nt][3] * inv1);
    }
}

// ---------------------------------------------------------------------------
extern "C" void kernel_launch(void* const* d_in, const int* in_sizes, int n_in,
                              void* d_out, int out_size) {
    const float* x      = (const float*)d_in[0];
    const float* rel    = (const float*)d_in[1];
    const float* w_qkv  = (const float*)d_in[2];
    const float* w_proj = (const float*)d_in[3];
    const float* w1     = (const float*)d_in[4];
    const float* b1     = (const float*)d_in[5];
    const float* w2     = (const float*)d_in[6];
    const float* b2     = (const float*)d_in[7];
    const float* w3     = (const float*)d_in[8];
    const float* b3     = (const float*)d_in[9];
    float* out = (float*)d_out;

    unsigned int *q32, *k32, *v32, *xp, *wqp, *wph, *ahi, *bias16;
    cudaGetSymbolAddress((void**)&q32, g_q32);
    cudaGetSymbolAddress((void**)&k32, g_k32);
    cudaGetSymbolAddress((void**)&v32, g_v32);
    cudaGetSymbolAddress((void**)&xp,  g_xp);
    cudaGetSymbolAddress((void**)&wqp, g_wqp);
    cudaGetSymbolAddress((void**)&wph, g_wph);
    cudaGetSymbolAddress((void**)&ahi, g_ahi);
    cudaGetSymbolAddress((void**)&bias16, g_bias16);

    constexpr int SM_PROJ = 2 * (64 * APu + 16 * BPu) * 4;   // 29,696 B
    cudaFuncSetAttribute(combo_qkv_rpb,
                         cudaFuncAttributeMaxDynamicSharedMemorySize, SM_QKV);
    cudaFuncSetAttribute(gemm_proj,
                         cudaFuncAttributeMaxDynamicSharedMemorySize, SM_PROJ);
    cudaFuncSetAttribute(flash10, cudaFuncAttributeMaxDynamicSharedMemorySize, FLASH_SMEM);

    // 1) vectorized packs (x + w_qkv)
    pack_all<<<(NPA4 + NPB4) / 256, 256>>>(x, w_qkv, xp, wqp);
    // 2) qkv GEMM || RPB MLP || w_proj pack (tail role)
    combo_qkv_rpb<<<NQKV_BLK + NRPB_BLK + NWP_BLK, 256, SM_QKV>>>(
        xp, wqp, q32, k32, (__half*)v32, rel, w1, b1, w2, b2, w3, b3, bias16,
        w_proj, wph);
    // 3) flash attention
    flash10<<<dim3(P / FQ, H), 256, FLASH_SMEM>>>(q32, k32, v32, bias16, ahi);
    // 4) proj (single fp16 MMA)
    gemm_proj<<<dim3(D / 128, P / 64), 128, SM_PROJ>>>(
        ahi, wph, out, P, D, D);
}